// round 1
// baseline (speedup 1.0000x reference)
#include <cuda_runtime.h>
#include <cstdint>
#include <cstddef>

#define NB 16
#define C_ 256
#define IC_ 128
#define HW_ 4096
#define NN 2048

// ---------- scratch (device globals; no allocation) ----------
__device__ float g_phi[(size_t)NB * IC_ * HW_];    // viewed as [b][256][2048]
__device__ float g_theta[(size_t)NB * IC_ * HW_];
__device__ float g_gv[(size_t)NB * IC_ * HW_];
__device__ float g_O[(size_t)NB * IC_ * HW_];      // attention output, [b][256][2048] == [b][128][4096]
__device__ float g_S[(size_t)NB * NN * NN];        // 268 MB scores
__device__ unsigned g_cmu[NB * NN];                // encoded column max
__device__ float g_Z[NB * NN];                     // column sum of exp
__device__ float g_cm[NB * NN];                    // decoded column max
__device__ float g_iz[NB * NN];                    // 1/Z

// monotone float<->uint encoding for atomic max over signed floats
__device__ __forceinline__ unsigned encf(float f) {
    unsigned u = __float_as_uint(f);
    return (u & 0x80000000u) ? ~u : (u | 0x80000000u);
}
__device__ __forceinline__ float decf(unsigned u) {
    return __uint_as_float((u & 0x80000000u) ? (u & 0x7fffffffu) : ~u);
}

#define MICROKERNEL(As, Bs, acc, tx, ty)                              \
    _Pragma("unroll")                                                 \
    for (int kk = 0; kk < 8; kk++) {                                  \
        float4 a0 = *(const float4*)&As[kk][(ty)*8];                  \
        float4 a1 = *(const float4*)&As[kk][(ty)*8 + 4];              \
        float4 b0 = *(const float4*)&Bs[kk][(tx)*8];                  \
        float4 b1 = *(const float4*)&Bs[kk][(tx)*8 + 4];              \
        float ra[8] = {a0.x,a0.y,a0.z,a0.w,a1.x,a1.y,a1.z,a1.w};      \
        float rb[8] = {b0.x,b0.y,b0.z,b0.w,b1.x,b1.y,b1.z,b1.w};      \
        _Pragma("unroll")                                             \
        for (int i = 0; i < 8; i++)                                   \
            _Pragma("unroll")                                         \
            for (int j = 0; j < 8; j++)                               \
                acc[i][j] = fmaf(ra[i], rb[j], acc[i][j]);            \
    }

// ---------- k0: init colmax / Z ----------
__global__ void k_init() {
    int i = blockIdx.x * blockDim.x + threadIdx.x;
    if (i < NB * NN) {
        g_cmu[i] = 0x00800000u;  // encf(-FLT_MAX)
        g_Z[i] = 0.0f;
    }
}

// ---------- k1: projections  Y[128,4096] = W[128,256] @ X[256,4096] + b ----------
__global__ void __launch_bounds__(256) k_proj(
    const float* __restrict__ x,
    const float* __restrict__ w_phi, const float* __restrict__ b_phi,
    const float* __restrict__ w_theta, const float* __restrict__ b_theta,
    const float* __restrict__ w_g, const float* __restrict__ b_g)
{
    int b = blockIdx.z;
    int p = blockIdx.y;  // 0=phi 1=theta 2=g
    const float* W    = (p == 0) ? w_phi  : (p == 1) ? w_theta : w_g;
    const float* bias = (p == 0) ? b_phi  : (p == 1) ? b_theta : b_g;
    float* Y = ((p == 0) ? g_phi : (p == 1) ? g_theta : g_gv) + (size_t)b * IC_ * HW_;
    const float* X = x + (size_t)b * C_ * HW_;
    int nblk = blockIdx.x * 128;

    __shared__ float As[8][128];
    __shared__ float Bs[8][128];
    int tid = threadIdx.x;
    int tx = tid & 15, ty = tid >> 4;
    float acc[8][8] = {};

    int arow = tid >> 1, ak4 = (tid & 1) * 4;   // A: [128 rows][8 k]
    int bk = tid >> 5, bn4 = (tid & 31) * 4;    // B: [8 k][128 n]

    for (int kt = 0; kt < C_; kt += 8) {
        float4 av = *(const float4*)(W + arow * C_ + kt + ak4);
        float4 bv = *(const float4*)(X + (size_t)(kt + bk) * HW_ + nblk + bn4);
        As[ak4 + 0][arow] = av.x; As[ak4 + 1][arow] = av.y;
        As[ak4 + 2][arow] = av.z; As[ak4 + 3][arow] = av.w;
        *(float4*)&Bs[bk][bn4] = bv;
        __syncthreads();
        MICROKERNEL(As, Bs, acc, tx, ty);
        __syncthreads();
    }
    #pragma unroll
    for (int i = 0; i < 8; i++) {
        int r = ty * 8 + i;
        float bi = bias[r];
        float4 o0 = make_float4(acc[i][0]+bi, acc[i][1]+bi, acc[i][2]+bi, acc[i][3]+bi);
        float4 o1 = make_float4(acc[i][4]+bi, acc[i][5]+bi, acc[i][6]+bi, acc[i][7]+bi);
        *(float4*)(Y + (size_t)r * HW_ + nblk + tx * 8)     = o0;
        *(float4*)(Y + (size_t)r * HW_ + nblk + tx * 8 + 4) = o1;
    }
}

// ---------- k2: S[n,m] = sum_c theta2[c,n] * phi2[c,m], + per-tile column max ----------
__global__ void __launch_bounds__(256) k_scores()
{
    int b = blockIdx.z;
    const float* Th = g_theta + (size_t)b * C_ * NN;  // [256][2048]
    const float* Ph = g_phi   + (size_t)b * C_ * NN;
    float* Sb = g_S + (size_t)b * NN * NN;
    int nblk = blockIdx.y * 128;  // rows of S (n)
    int mblk = blockIdx.x * 128;  // cols of S (m)

    __shared__ float As[8][128];
    __shared__ float Bs[8][128];
    __shared__ float red[16][132];

    int tid = threadIdx.x;
    int tx = tid & 15, ty = tid >> 4;
    float acc[8][8] = {};

    int lk = tid >> 5, lc4 = (tid & 31) * 4;  // both ops are K-major: [8 k][128 cols]

    for (int kt = 0; kt < C_; kt += 8) {
        float4 av = *(const float4*)(Th + (size_t)(kt + lk) * NN + nblk + lc4);
        float4 bv = *(const float4*)(Ph + (size_t)(kt + lk) * NN + mblk + lc4);
        *(float4*)&As[lk][lc4] = av;
        *(float4*)&Bs[lk][lc4] = bv;
        __syncthreads();
        MICROKERNEL(As, Bs, acc, tx, ty);
        __syncthreads();
    }
    // write S tile
    #pragma unroll
    for (int i = 0; i < 8; i++) {
        float4 o0 = make_float4(acc[i][0], acc[i][1], acc[i][2], acc[i][3]);
        float4 o1 = make_float4(acc[i][4], acc[i][5], acc[i][6], acc[i][7]);
        size_t row = (size_t)(nblk + ty * 8 + i) * NN + mblk + tx * 8;
        *(float4*)(Sb + row)     = o0;
        *(float4*)(Sb + row + 4) = o1;
    }
    // per-block column max -> atomic global column max
    float cm8[8];
    #pragma unroll
    for (int j = 0; j < 8; j++) {
        float m = acc[0][j];
        #pragma unroll
        for (int i = 1; i < 8; i++) m = fmaxf(m, acc[i][j]);
        cm8[j] = m;
    }
    #pragma unroll
    for (int j = 0; j < 8; j++) red[ty][tx * 8 + j] = cm8[j];
    __syncthreads();
    if (ty == 0) {
        #pragma unroll
        for (int j = 0; j < 8; j++) {
            int col = tx * 8 + j;
            float m = red[0][col];
            #pragma unroll
            for (int r = 1; r < 16; r++) m = fmaxf(m, red[r][col]);
            atomicMax(&g_cmu[b * NN + mblk + col], encf(m));
        }
    }
}

// ---------- k3: Z[m] = sum_n exp(S[n,m] - max[m]) ----------
__global__ void __launch_bounds__(256) k_sumexp()
{
    int b = blockIdx.z;
    int m = blockIdx.x * 256 + threadIdx.x;
    int n0 = blockIdx.y * 512;
    float mx = decf(g_cmu[b * NN + m]);
    const float* Sb = g_S + (size_t)b * NN * NN;
    float s = 0.0f;
    #pragma unroll 8
    for (int n = n0; n < n0 + 512; n++)
        s += __expf(Sb[(size_t)n * NN + m] - mx);
    atomicAdd(&g_Z[b * NN + m], s);
}

// ---------- k3b: finalize cm, 1/Z ----------
__global__ void k_finish() {
    int i = blockIdx.x * blockDim.x + threadIdx.x;
    if (i < NB * NN) {
        g_cm[i] = decf(g_cmu[i]);
        g_iz[i] = 1.0f / g_Z[i];
    }
}

// ---------- k4: O2[c,n] = sum_m (g2[c,m]*izZ[m]) * exp(S[n,m]-cm[m]) ----------
__global__ void __launch_bounds__(256) k_pv()
{
    int b = blockIdx.z;
    const float* G  = g_gv + (size_t)b * C_ * NN;   // A[c][m]
    const float* Sb = g_S  + (size_t)b * NN * NN;   // B[n][m]
    float* O = g_O + (size_t)b * IC_ * HW_;         // [256][2048]
    const float* cm = g_cm + b * NN;
    const float* iz = g_iz + b * NN;
    int cblk = blockIdx.y * 128;
    int nblk = blockIdx.x * 128;

    __shared__ float As[8][128];   // [m_k][c]
    __shared__ float Bs[8][128];   // [m_k][n]
    int tid = threadIdx.x;
    int tx = tid & 15, ty = tid >> 4;
    float acc[8][8] = {};

    int lrow = tid >> 1, lm4 = (tid & 1) * 4;  // both row-major with K(=m) contiguous

    for (int kt = 0; kt < NN; kt += 8) {
        float4 av  = *(const float4*)(G  + (size_t)(cblk + lrow) * NN + kt + lm4);
        float4 iz4 = *(const float4*)(iz + kt + lm4);
        float4 sv  = *(const float4*)(Sb + (size_t)(nblk + lrow) * NN + kt + lm4);
        float4 cm4 = *(const float4*)(cm + kt + lm4);
        As[lm4 + 0][lrow] = av.x * iz4.x;
        As[lm4 + 1][lrow] = av.y * iz4.y;
        As[lm4 + 2][lrow] = av.z * iz4.z;
        As[lm4 + 3][lrow] = av.w * iz4.w;
        Bs[lm4 + 0][lrow] = __expf(sv.x - cm4.x);
        Bs[lm4 + 1][lrow] = __expf(sv.y - cm4.y);
        Bs[lm4 + 2][lrow] = __expf(sv.z - cm4.z);
        Bs[lm4 + 3][lrow] = __expf(sv.w - cm4.w);
        __syncthreads();
        MICROKERNEL(As, Bs, acc, tx, ty);
        __syncthreads();
    }
    #pragma unroll
    for (int i = 0; i < 8; i++) {
        float4 o0 = make_float4(acc[i][0], acc[i][1], acc[i][2], acc[i][3]);
        float4 o1 = make_float4(acc[i][4], acc[i][5], acc[i][6], acc[i][7]);
        size_t row = (size_t)(cblk + ty * 8 + i) * NN + nblk + tx * 8;
        *(float4*)(O + row)     = o0;
        *(float4*)(O + row + 4) = o1;
    }
}

// ---------- k5: out = w_mask @ O + b_mask + x ----------
__global__ void __launch_bounds__(256) k_mask(
    const float* __restrict__ x,
    const float* __restrict__ w_mask, const float* __restrict__ b_mask,
    float* __restrict__ out)
{
    int b = blockIdx.z;
    int rowblk = blockIdx.y * 128;   // output channel tile (0 or 128)
    int nblk = blockIdx.x * 128;
    const float* O = g_O + (size_t)b * IC_ * HW_;  // [128][4096]

    __shared__ float As[8][128];
    __shared__ float Bs[8][128];
    int tid = threadIdx.x;
    int tx = tid & 15, ty = tid >> 4;
    float acc[8][8] = {};

    int arow = tid >> 1, ak4 = (tid & 1) * 4;
    int bk = tid >> 5, bn4 = (tid & 31) * 4;

    for (int kt = 0; kt < IC_; kt += 8) {
        float4 av = *(const float4*)(w_mask + (rowblk + arow) * IC_ + kt + ak4);
        float4 bv = *(const float4*)(O + (size_t)(kt + bk) * HW_ + nblk + bn4);
        As[ak4 + 0][arow] = av.x; As[ak4 + 1][arow] = av.y;
        As[ak4 + 2][arow] = av.z; As[ak4 + 3][arow] = av.w;
        *(float4*)&Bs[bk][bn4] = bv;
        __syncthreads();
        MICROKERNEL(As, Bs, acc, tx, ty);
        __syncthreads();
    }
    #pragma unroll
    for (int i = 0; i < 8; i++) {
        int r = rowblk + ty * 8 + i;
        float bi = b_mask[r];
        size_t base = ((size_t)b * C_ + r) * HW_ + nblk + tx * 8;
        float4 x0 = *(const float4*)(x + base);
        float4 x1 = *(const float4*)(x + base + 4);
        float4 o0 = make_float4(acc[i][0]+bi+x0.x, acc[i][1]+bi+x0.y,
                                acc[i][2]+bi+x0.z, acc[i][3]+bi+x0.w);
        float4 o1 = make_float4(acc[i][4]+bi+x1.x, acc[i][5]+bi+x1.y,
                                acc[i][6]+bi+x1.z, acc[i][7]+bi+x1.w);
        *(float4*)(out + base)     = o0;
        *(float4*)(out + base + 4) = o1;
    }
}

extern "C" void kernel_launch(void* const* d_in, const int* in_sizes, int n_in,
                              void* d_out, int out_size)
{
    const float* x       = (const float*)d_in[0];
    const float* w_phi   = (const float*)d_in[1];
    const float* b_phi   = (const float*)d_in[2];
    const float* w_theta = (const float*)d_in[3];
    const float* b_theta = (const float*)d_in[4];
    const float* w_g     = (const float*)d_in[5];
    const float* b_g     = (const float*)d_in[6];
    const float* w_mask  = (const float*)d_in[7];
    const float* b_mask  = (const float*)d_in[8];
    float* out = (float*)d_out;

    k_init<<<128, 256>>>();
    k_proj<<<dim3(32, 3, NB), 256>>>(x, w_phi, b_phi, w_theta, b_theta, w_g, b_g);
    k_scores<<<dim3(16, 16, NB), 256>>>();
    k_sumexp<<<dim3(8, 4, NB), 256>>>();
    k_finish<<<128, 256>>>();
    k_pv<<<dim3(16, 2, NB), 256>>>();
    k_mask<<<dim3(32, 2, NB), 256>>>(x, w_mask, b_mask, out);
}

// round 3
// speedup vs baseline: 2.1277x; 2.1277x over previous
#include <cuda_runtime.h>
#include <cuda_bf16.h>
#include <cstdint>
#include <cstddef>

#define NB 16
#define C_ 256
#define IC_ 128
#define HW_ 4096
#define NN 2048
#define KB 64
#define SMEM_DYN (66048 + 1536)

// ---------------- scratch ----------------
__device__ float    g_gv[(size_t)NB * C_ * NN];    // g2 [b][c(flat ic*4096+hw)] fp32
__device__ uint32_t g_phT[(size_t)NB * NN * C_];   // phi^T  [b][m][c'] packed (hi,lo) bf16
__device__ uint32_t g_thT[(size_t)NB * NN * C_];   // theta^T[b][n][c']
__device__ uint32_t g_xT[(size_t)NB * HW_ * C_];   // x^T    [b][hw][c]
__device__ uint32_t g_OT[(size_t)NB * HW_ * IC_];  // O^T    [b][hw][ic]
__device__ float    g_S[(size_t)NB * NN * NN];     // S fp32; overwritten by packed P
__device__ unsigned g_cmu[NB * NN];
__device__ float    g_Z[NB * NN];
__device__ float    g_iz[NB * NN];

// ---------------- helpers ----------------
__device__ __forceinline__ uint32_t smem_u32(const void* p) {
    return (uint32_t)__cvta_generic_to_shared(p);
}
__device__ __forceinline__ uint32_t swz(uint32_t off) { return off ^ ((off >> 3) & 0x70); }
__device__ __forceinline__ void sts64(uint32_t a, uint32_t x, uint32_t y) {
    asm volatile("st.shared.v2.b32 [%0], {%1, %2};" :: "r"(a), "r"(x), "r"(y) : "memory");
}
__device__ __forceinline__ void ldsm4(uint32_t a, uint32_t r[4]) {
    asm volatile("ldmatrix.sync.aligned.m8n8.x4.shared.b16 {%0,%1,%2,%3}, [%4];"
                 : "=r"(r[0]), "=r"(r[1]), "=r"(r[2]), "=r"(r[3]) : "r"(a));
}
__device__ __forceinline__ void mma16816(float d[4], const uint32_t a[4], uint32_t b0, uint32_t b1) {
    asm("mma.sync.aligned.m16n8k16.row.col.f32.bf16.bf16.f32 "
        "{%0,%1,%2,%3},{%4,%5,%6,%7},{%8,%9},{%0,%1,%2,%3};"
        : "+f"(d[0]), "+f"(d[1]), "+f"(d[2]), "+f"(d[3])
        : "r"(a[0]), "r"(a[1]), "r"(a[2]), "r"(a[3]), "r"(b0), "r"(b1));
}
__device__ __forceinline__ unsigned encf(float f) {
    unsigned u = __float_as_uint(f);
    return (u & 0x80000000u) ? ~u : (u | 0x80000000u);
}
__device__ __forceinline__ float decf(unsigned u) {
    return __uint_as_float((u & 0x80000000u) ? (u & 0x7fffffffu) : ~u);
}
__device__ __forceinline__ uint32_t pack_hl(float v) {
    __nv_bfloat16 h = __float2bfloat16(v);
    __nv_bfloat16 l = __float2bfloat16(v - __bfloat162float(h));
    return (uint32_t)__bfloat16_as_ushort(h) | ((uint32_t)__bfloat16_as_ushort(l) << 16);
}

// ---------------- tile fills (128 rows x 64 k, hi/lo planes, swizzled) ----------------
__device__ __forceinline__ void fill_u32(uint32_t sh, uint32_t sl,
    const uint32_t* __restrict__ src, int ld, int rowbase, int kt, int tid)
{
    #pragma unroll
    for (int it = 0; it < 8; it++) {
        int i = it * 256 + tid;
        int row = i >> 4;
        int k4 = (i & 15) * 4;
        uint4 v = *(const uint4*)(src + (size_t)(rowbase + row) * ld + kt + k4);
        uint32_t h0 = (v.x & 0xFFFFu) | (v.y << 16);
        uint32_t h1 = (v.z & 0xFFFFu) | (v.w << 16);
        uint32_t l0 = (v.x >> 16) | (v.y & 0xFFFF0000u);
        uint32_t l1 = (v.z >> 16) | (v.w & 0xFFFF0000u);
        uint32_t off = swz((uint32_t)(row * 128 + k4 * 2));
        sts64(sh + off, h0, h1);
        sts64(sl + off, l0, l1);
    }
}
template <bool SCALED>
__device__ __forceinline__ void fill_f32(uint32_t sh, uint32_t sl,
    const float* __restrict__ src, int ld, int rowbase, int kt,
    const float* __restrict__ scale, int tid)
{
    #pragma unroll
    for (int it = 0; it < 8; it++) {
        int i = it * 256 + tid;
        int row = i >> 4;
        int k4 = (i & 15) * 4;
        float4 v = *(const float4*)(src + (size_t)(rowbase + row) * ld + kt + k4);
        if (SCALED) {
            float4 s = *(const float4*)(scale + kt + k4);
            v.x *= s.x; v.y *= s.y; v.z *= s.z; v.w *= s.w;
        }
        uint32_t p0 = pack_hl(v.x), p1 = pack_hl(v.y), p2 = pack_hl(v.z), p3 = pack_hl(v.w);
        uint32_t h0 = (p0 & 0xFFFFu) | (p1 << 16);
        uint32_t h1 = (p2 & 0xFFFFu) | (p3 << 16);
        uint32_t l0 = (p0 >> 16) | (p1 & 0xFFFF0000u);
        uint32_t l1 = (p2 >> 16) | (p3 & 0xFFFF0000u);
        uint32_t off = swz((uint32_t)(row * 128 + k4 * 2));
        sts64(sh + off, h0, h1);
        sts64(sl + off, l0, l1);
    }
}

// ---------------- mma compute for one 128x128x64 block ----------------
__device__ __forceinline__ void compute_block(
    uint32_t sAh, uint32_t sAl, uint32_t sBh, uint32_t sBl,
    int wm, int wn, int lid, float acc[2][8][4])
{
    int a_m = lid & 15;
    int a_k = (lid >> 4) * 8;
    int b_n = (lid & 7) | ((lid & 16) >> 1);
    int b_k = lid & 8;
    #pragma unroll
    for (int ks = 0; ks < 4; ks++) {
        int kb = ks * 16;
        uint32_t Ah[2][4], Al[2][4];
        #pragma unroll
        for (int mf = 0; mf < 2; mf++) {
            uint32_t off = swz((uint32_t)((wm + mf * 16 + a_m) * 128 + (kb + a_k) * 2));
            ldsm4(sAh + off, Ah[mf]);
            ldsm4(sAl + off, Al[mf]);
        }
        #pragma unroll
        for (int nf2 = 0; nf2 < 4; nf2++) {
            uint32_t off = swz((uint32_t)((wn + nf2 * 16 + b_n) * 128 + (kb + b_k) * 2));
            uint32_t bh[4], bl[4];
            ldsm4(sBh + off, bh);
            ldsm4(sBl + off, bl);
            #pragma unroll
            for (int mf = 0; mf < 2; mf++) {
                #pragma unroll
                for (int q = 0; q < 2; q++) {
                    float* d = acc[mf][nf2 * 2 + q];
                    mma16816(d, Ah[mf], bh[2 * q], bh[2 * q + 1]);
                    mma16816(d, Ah[mf], bl[2 * q], bl[2 * q + 1]);
                    mma16816(d, Al[mf], bh[2 * q], bh[2 * q + 1]);
                }
            }
        }
    }
}

__device__ __forceinline__ void store_sD(float (*sD)[129], int wm, int wn, int lid,
                                         float acc[2][8][4])
{
    int r = lid >> 2, c2 = (lid & 3) * 2;
    #pragma unroll
    for (int mf = 0; mf < 2; mf++) {
        #pragma unroll
        for (int nf = 0; nf < 8; nf++) {
            int row = wm + mf * 16 + r;
            int col = wn + nf * 8 + c2;
            sD[col][row]     = acc[mf][nf][0];
            sD[col + 1][row] = acc[mf][nf][1];
            sD[col][row + 8]     = acc[mf][nf][2];
            sD[col + 1][row + 8] = acc[mf][nf][3];
        }
    }
}

#define GEMM_PROLOGUE() \
    extern __shared__ __align__(16) char dsm[]; \
    uint32_t sraw = smem_u32(dsm); \
    uint32_t sbase = (sraw + 1023) & ~1023u; \
    uint32_t sAh = sbase, sAl = sbase + 16384, sBh = sbase + 32768, sBl = sbase + 49152; \
    float (*sD)[129] = (float (*)[129])(dsm + (sbase - sraw)); \
    int tid = threadIdx.x, wid = tid >> 5, lid = tid & 31; \
    int wm = (wid >> 1) * 32, wn = (wid & 1) * 64; \
    float acc[2][8][4] = {};

// ---------- k_init ----------
__global__ void k_init() {
    int i = blockIdx.x * blockDim.x + threadIdx.x;
    if (i < NB * NN) { g_cmu[i] = 0x00800000u; g_Z[i] = 0.0f; }
}

// ---------- k_xt: x[b][c][hw] -> xT[b][hw][c] packed ----------
__global__ void k_xt(const float* __restrict__ x) {
    __shared__ float t[32][33];
    int b = blockIdx.z;
    int hw0 = blockIdx.x * 32, c0 = blockIdx.y * 32;
    int tx = threadIdx.x, ty = threadIdx.y;
    #pragma unroll
    for (int i = 0; i < 4; i++)
        t[ty + i * 8][tx] = x[((size_t)b * C_ + c0 + ty + i * 8) * HW_ + hw0 + tx];
    __syncthreads();
    #pragma unroll
    for (int i = 0; i < 4; i++) {
        int hw = hw0 + ty + i * 8;
        g_xT[((size_t)b * HW_ + hw) * C_ + c0 + tx] = pack_hl(t[tx][ty + i * 8]);
    }
}

// ---------- k_projT ----------
__global__ void __launch_bounds__(256, 2) k_projT(
    const float* __restrict__ w_phi, const float* __restrict__ b_phi,
    const float* __restrict__ w_theta, const float* __restrict__ b_theta,
    const float* __restrict__ w_g, const float* __restrict__ b_g)
{
    __shared__ float s_bias[128];
    int b = blockIdx.z, p = blockIdx.y;
    int nblk = blockIdx.x * 128;
    const float* W    = p == 0 ? w_phi : p == 1 ? w_theta : w_g;
    const float* bias = p == 0 ? b_phi : p == 1 ? b_theta : b_g;
    const uint32_t* xT = g_xT + (size_t)b * HW_ * C_;

    GEMM_PROLOGUE();
    if (tid < 128) s_bias[tid] = bias[tid];
    for (int kt = 0; kt < C_; kt += KB) {
        fill_f32<false>(sAh, sAl, W, C_, 0, kt, nullptr, tid);
        fill_u32(sBh, sBl, xT, C_, nblk, kt, tid);
        __syncthreads();
        compute_block(sAh, sAl, sBh, sBl, wm, wn, lid, acc);
        __syncthreads();
    }
    store_sD(sD, wm, wn, lid, acc);
    __syncthreads();

    if (p < 2) {
        // dst[n][c'] with c' = half*128 + ic  (k-permutation, applied to both phi & theta)
        uint32_t* dst = (p == 0 ? g_phT : g_thT) + (size_t)b * NN * C_;
        int half = nblk >> 11;
        int n0 = nblk & 2047;
        int n = tid >> 1, ich = (tid & 1) * 64;
        uint32_t* drow = dst + (size_t)(n0 + n) * C_ + half * 128 + ich;
        #pragma unroll
        for (int j = 0; j < 64; j += 4) {
            uint4 v;
            v.x = pack_hl(sD[n][ich + j + 0] + s_bias[ich + j + 0]);
            v.y = pack_hl(sD[n][ich + j + 1] + s_bias[ich + j + 1]);
            v.z = pack_hl(sD[n][ich + j + 2] + s_bias[ich + j + 2]);
            v.w = pack_hl(sD[n][ich + j + 3] + s_bias[ich + j + 3]);
            *(uint4*)(drow + j) = v;
        }
    } else {
        int ic = tid >> 1, nh = (tid & 1) * 64;
        float bi = s_bias[ic];
        float* drow = g_gv + (size_t)b * C_ * NN + (size_t)ic * HW_ + nblk + nh;
        #pragma unroll
        for (int j = 0; j < 64; j += 4) {
            float4 v = make_float4(sD[nh + j + 0][ic] + bi, sD[nh + j + 1][ic] + bi,
                                   sD[nh + j + 2][ic] + bi, sD[nh + j + 3][ic] + bi);
            *(float4*)(drow + j) = v;
        }
    }
}

// ---------- k_scores: D[m][n] = S[n][m]; + column max over n ----------
__global__ void __launch_bounds__(256, 2) k_scores() {
    int b = blockIdx.z;
    int mblk = blockIdx.x * 128, nblk = blockIdx.y * 128;
    const uint32_t* A = g_phT + (size_t)b * NN * C_;
    const uint32_t* B = g_thT + (size_t)b * NN * C_;
    float* Sb = g_S + (size_t)b * NN * NN;

    GEMM_PROLOGUE();
    for (int kt = 0; kt < C_; kt += KB) {
        fill_u32(sAh, sAl, A, C_, mblk, kt, tid);
        fill_u32(sBh, sBl, B, C_, nblk, kt, tid);
        __syncthreads();
        compute_block(sAh, sAl, sBh, sBl, wm, wn, lid, acc);
        __syncthreads();
    }
    store_sD(sD, wm, wn, lid, acc);
    __syncthreads();

    int n = tid >> 1, mh = (tid & 1) * 64;
    float* srow = Sb + (size_t)(nblk + n) * NN + mblk + mh;
    #pragma unroll
    for (int j = 0; j < 64; j += 4) {
        float4 v = make_float4(sD[n][mh + j], sD[n][mh + j + 1],
                               sD[n][mh + j + 2], sD[n][mh + j + 3]);
        *(float4*)(srow + j) = v;
    }
    __syncthreads();
    if (tid < 128) {
        float mx = -3.4e38f;
        #pragma unroll 8
        for (int n2 = 0; n2 < 128; n2++) mx = fmaxf(mx, sD[n2][tid]);
        atomicMax(&g_cmu[b * NN + mblk + tid], encf(mx));
    }
}

// ---------- k_sumexp: P = exp(S - cmax[m]) in place (packed), Z accum ----------
__global__ void __launch_bounds__(256) k_sumexp() {
    int b = blockIdx.z;
    int m = blockIdx.x * 256 + threadIdx.x;
    int n0 = blockIdx.y * 512;
    float mxv = decf(g_cmu[b * NN + m]);
    float* Sb = g_S + (size_t)b * NN * NN;
    uint32_t* Pb = (uint32_t*)Sb;
    float s = 0.0f;
    for (int n = n0; n < n0 + 512; n++) {
        size_t idx = (size_t)n * NN + m;
        float e = __expf(Sb[idx] - mxv);
        s += e;
        Pb[idx] = pack_hl(e);
    }
    atomicAdd(&g_Z[b * NN + m], s);
}

// ---------- k_finish ----------
__global__ void k_finish() {
    int i = blockIdx.x * blockDim.x + threadIdx.x;
    if (i < NB * NN) g_iz[i] = 1.0f / g_Z[i];
}

// ---------- k_pv: D[c][n] = sum_m g[c][m]*iz[m]*P[n][m]; writes O^T packed ----------
__global__ void __launch_bounds__(256, 2) k_pv() {
    int b = blockIdx.z;
    int cblk = blockIdx.y * 128, nblk = blockIdx.x * 128;
    const float* A = g_gv + (size_t)b * C_ * NN;     // [c][m] flat
    const uint32_t* B = (const uint32_t*)(g_S + (size_t)b * NN * NN);  // P[n][m]
    const float* scale = g_iz + b * NN;

    GEMM_PROLOGUE();
    for (int kt = 0; kt < NN; kt += KB) {
        fill_f32<true>(sAh, sAl, A, NN, cblk, kt, scale, tid);
        fill_u32(sBh, sBl, B, NN, nblk, kt, tid);
        __syncthreads();
        compute_block(sAh, sAl, sBh, sBl, wm, wn, lid, acc);
        __syncthreads();
    }
    store_sD(sD, wm, wn, lid, acc);
    __syncthreads();

    // OT[hw][ic], hw = (c&1)*2048 + nblk + n, ic = c>>1
    int n = tid >> 1, par = tid & 1;
    uint32_t* drow = g_OT + (size_t)b * HW_ * IC_
                   + (size_t)(par * 2048 + nblk + n) * IC_ + (cblk >> 1);
    #pragma unroll
    for (int j = 0; j < 64; j += 4) {
        uint4 v;
        v.x = pack_hl(sD[n][2 * (j + 0) + par]);
        v.y = pack_hl(sD[n][2 * (j + 1) + par]);
        v.z = pack_hl(sD[n][2 * (j + 2) + par]);
        v.w = pack_hl(sD[n][2 * (j + 3) + par]);
        *(uint4*)(drow + j) = v;
    }
}

// ---------- k_mask: out = w_mask @ O + b_mask + x ----------
__global__ void __launch_bounds__(256, 2) k_mask(
    const float* __restrict__ x,
    const float* __restrict__ w_mask, const float* __restrict__ b_mask,
    float* __restrict__ out)
{
    __shared__ float s_bias[128];
    int b = blockIdx.z;
    int rowblk = blockIdx.y * 128, nblk = blockIdx.x * 128;
    const uint32_t* B = g_OT + (size_t)b * HW_ * IC_;

    GEMM_PROLOGUE();
    if (tid < 128) s_bias[tid] = b_mask[rowblk + tid];
    for (int kt = 0; kt < IC_; kt += KB) {
        fill_f32<false>(sAh, sAl, w_mask, IC_, rowblk, kt, nullptr, tid);
        fill_u32(sBh, sBl, B, IC_, nblk, kt, tid);
        __syncthreads();
        compute_block(sAh, sAl, sBh, sBl, wm, wn, lid, acc);
        __syncthreads();
    }
    store_sD(sD, wm, wn, lid, acc);
    __syncthreads();

    int co = tid >> 1, nh = (tid & 1) * 64;
    float bi = s_bias[co];
    size_t base = ((size_t)b * C_ + rowblk + co) * HW_ + nblk + nh;
    #pragma unroll
    for (int j = 0; j < 64; j += 4) {
        float4 xv = *(const float4*)(x + base + j);
        float4 v = make_float4(sD[nh + j + 0][co] + bi + xv.x,
                               sD[nh + j + 1][co] + bi + xv.y,
                               sD[nh + j + 2][co] + bi + xv.z,
                               sD[nh + j + 3][co] + bi + xv.w);
        *(float4*)(out + base + j) = v;
    }
}

extern "C" void kernel_launch(void* const* d_in, const int* in_sizes, int n_in,
                              void* d_out, int out_size)
{
    const float* x       = (const float*)d_in[0];
    const float* w_phi   = (const float*)d_in[1];
    const float* b_phi   = (const float*)d_in[2];
    const float* w_theta = (const float*)d_in[3];
    const float* b_theta = (const float*)d_in[4];
    const float* w_g     = (const float*)d_in[5];
    const float* b_g     = (const float*)d_in[6];
    const float* w_mask  = (const float*)d_in[7];
    const float* b_mask  = (const float*)d_in[8];
    float* out = (float*)d_out;

    cudaFuncSetAttribute(k_projT,  cudaFuncAttributeMaxDynamicSharedMemorySize, SMEM_DYN);
    cudaFuncSetAttribute(k_scores, cudaFuncAttributeMaxDynamicSharedMemorySize, SMEM_DYN);
    cudaFuncSetAttribute(k_pv,     cudaFuncAttributeMaxDynamicSharedMemorySize, SMEM_DYN);
    cudaFuncSetAttribute(k_mask,   cudaFuncAttributeMaxDynamicSharedMemorySize, SMEM_DYN);

    k_init<<<128, 256>>>();
    k_xt<<<dim3(128, 8, NB), dim3(32, 8)>>>(x);
    k_projT<<<dim3(32, 3, NB), 256, SMEM_DYN>>>(w_phi, b_phi, w_theta, b_theta, w_g, b_g);
    k_scores<<<dim3(16, 16, NB), 256, SMEM_DYN>>>();
    k_sumexp<<<dim3(8, 4, NB), 256>>>();
    k_finish<<<128, 256>>>();
    k_pv<<<dim3(16, 2, NB), 256, SMEM_DYN>>>();
    k_mask<<<dim3(32, 2, NB), 256, SMEM_DYN>>>(x, w_mask, b_mask, out);
}